// round 1
// baseline (speedup 1.0000x reference)
#include <cuda_runtime.h>
#include <stdint.h>
#include <math.h>

#define NA 180
#define NH 256
#define NW 256
#define ND 256
#define NB 16
#define NT 5
#define NP (NH*NW)
#define MPI 3.14159265358979323846

// ---------------- device globals (no allocation allowed) ----------------
__device__ float g_C[NA];
__device__ float g_S[NA];
__device__ int   g_row[NA];
__device__ __align__(16) uint8_t g_bins[NA * NP];          // 11.8 MB
__device__ ushort4 g_meta[NA * NH];                         // xlo, xhi, leftbin, rightbin
__device__ __align__(64) float g_img[NP * NB];              // 4 MB, [pixel][batch]
__device__ __align__(64) float g_P[NH * 257 * NB];          // row prefix sums [y][x][b]
__device__ __align__(64) float g_R[NA * ND * NB];           // residual [a][d][b]
__device__ unsigned g_maxbits;

// ---------------- init ----------------
__global__ void k_init() {
    int i = blockIdx.x * blockDim.x + threadIdx.x;
    for (int j = i; j < NP * NB; j += gridDim.x * blockDim.x) g_img[j] = 0.0f;
    if (i == 0) g_maxbits = 0u;
}

// angles / rows / trig, replicating numpy linspace + f32 ops
__global__ void k_angles() {
    int i = threadIdx.x;
    if (i < NA) {
        double ad = (double)i * (MPI / 179.0);
        float ang = (float)ad;
        if (i == NA - 1) ang = (float)MPI;              // linspace endpoint
        g_C[i] = (float)cos((double)ang);
        g_S[i] = (float)sin((double)ang);
        float r = __fmul_rn(__fdiv_rn(ang, (float)MPI), 179.0f);
        g_row[i] = (int)r;                               // trunc, nonneg
    }
}

// bins (exact f32 emulation) + per-(angle,row) run metadata
__global__ __launch_bounds__(256) void k_bins() {
    int a = blockIdx.x, y = threadIdx.x;
    const float TWO_PI_F = (float)(2.0 * MPI);
    float c = g_C[a], s = g_S[a];
    float t = __fmul_rn((float)y - 128.0f, s);
    uint8_t* brow = g_bins + (size_t)(a * NH + y) * NW;
    int prev = -1, lb = 0, xlo = 256, lastChange = 0;
    unsigned pk = 0;
    for (int x = 0; x < NW; x++) {
        float xc = (float)x - 128.0f;
        float rot = __fadd_rn(__fmul_rn(xc, c), t);
        float v = __fmul_rn(__fdiv_rn(rot, TWO_PI_F), 256.0f);
        v = truncf(v);
        v = fminf(fmaxf(v, 0.0f), 255.0f);
        int bin = (int)v;
        if (x == 0) { lb = bin; prev = bin; }
        else if (bin != prev) {
            if (xlo == 256) xlo = x;
            lastChange = x;
            prev = bin;
        }
        pk |= ((unsigned)bin) << (8 * (x & 3));
        if ((x & 3) == 3) { *(unsigned*)(brow + x - 3) = pk; pk = 0; }
    }
    int rb = prev;
    int xhi = lastChange;            // 0 if row constant
    if (xhi < xlo) xhi = xlo;        // constant row: all "left"
    g_meta[a * NH + y] = make_ushort4((unsigned short)xlo, (unsigned short)xhi,
                                      (unsigned short)lb, (unsigned short)rb);
}

// per-row, per-batch inclusive prefix sums of image: P[y][x][b] = sum img[y][0..x)
__global__ __launch_bounds__(256) void k_prefix() {
    __shared__ float sh[256 * 17];
    int y = blockIdx.x, t = threadIdx.x;
    const float* row = g_img + (size_t)y * NW * NB;
    for (int i = t; i < NW * NB; i += 256) {
        int x = i >> 4, b = i & 15;
        sh[x * 17 + b] = row[i];
    }
    __syncthreads();
    int w = t >> 5, lane = t & 31;
    for (int ch = w * 2; ch < w * 2 + 2; ch++) {
        float carry = 0.0f;
        for (int seg = 0; seg < 8; seg++) {
            int x = seg * 32 + lane;
            float v = sh[x * 17 + ch];
            #pragma unroll
            for (int off = 1; off < 32; off <<= 1) {
                float n = __shfl_up_sync(0xffffffffu, v, off);
                if (lane >= off) v += n;
            }
            v += carry;
            g_P[((size_t)y * 257 + x + 1) * NB + ch] = v;
            carry = __shfl_sync(0xffffffffu, v, 31);
        }
    }
    if (t < NB) g_P[((size_t)y * 257) * NB + t] = 0.0f;
}

// forward projection + residual. One block per angle.
__global__ __launch_bounds__(256) void k_fp(const float* __restrict__ sino) {
    __shared__ float hist[256 * 17];
    int a = blockIdx.x, t = threadIdx.x;
    for (int i = t; i < 256 * 17; i += 256) hist[i] = 0.0f;
    __syncthreads();
    int w = t >> 5, lane = t & 31, b = lane & 15, half = lane >> 4;
    float acc0 = 0.0f, acc255 = 0.0f;
    for (int y = w; y < NH; y += 8) {
        ushort4 m = g_meta[a * NH + y];
        int xlo = m.x, xhi = m.y, lb = m.z, rb = m.w;
        const float* Prow = g_P + (size_t)y * 257 * NB;
        float v; int sb;
        if (half == 0) { v = Prow[xlo * NB + b]; sb = lb; }
        else           { v = Prow[256 * NB + b] - Prow[xhi * NB + b]; sb = rb; }
        if (sb == 0) acc0 += v;
        else if (sb == 255) acc255 += v;
        else atomicAdd(&hist[sb * 17 + b], v);
        // interior pixels, per-pixel bins
        const uint8_t* brow = g_bins + (size_t)(a * NH + y) * NW;
        const float* irow = g_img + (size_t)y * NW * NB;
        for (int x = xlo + half; x < xhi; x += 2) {
            int bin = brow[x];
            atomicAdd(&hist[bin * 17 + b], irow[x * NB + b]);
        }
    }
    atomicAdd(&hist[0 * 17 + b], acc0);
    atomicAdd(&hist[255 * 17 + b], acc255);
    __syncthreads();
    // residual R[a][d][b] = sino[b][row][d] - fp
    int row = g_row[a];
    int d = t;
    float* Rd = g_R + (size_t)(a * ND + d) * NB;
    #pragma unroll
    for (int bb = 0; bb < NB; bb++) {
        float sv = sino[(size_t)bb * (NA * ND) + row * ND + d];
        Rd[bb] = sv - hist[d * 17 + bb];
    }
}

// back-projection + image update. One block per image row.
__global__ __launch_bounds__(256) void k_bp() {
    __shared__ float Dsh[257 * 17];
    __shared__ ushort4 sm[NA];
    int y = blockIdx.x, t = threadIdx.x;
    for (int i = t; i < 257 * 17; i += 256) Dsh[i] = 0.0f;
    if (t < NA) sm[t] = g_meta[t * NH + y];
    __syncthreads();
    // Phase A: saturated step contributions as difference array
    if (t < NA) {
        ushort4 m = sm[t];
        int xlo = m.x, xhi = m.y, lb = m.z, rb = m.w;
        const float* Ra = g_R + (size_t)t * ND * NB;
        if (xlo > 0) {
            const float* rl = Ra + lb * NB;
            #pragma unroll
            for (int bb = 0; bb < NB; bb++) {
                float v = rl[bb];
                atomicAdd(&Dsh[0 * 17 + bb], v);
                atomicAdd(&Dsh[xlo * 17 + bb], -v);
            }
        }
        if (xhi < 256) {
            const float* rr = Ra + rb * NB;
            #pragma unroll
            for (int bb = 0; bb < NB; bb++)
                atomicAdd(&Dsh[xhi * 17 + bb], rr[bb]);
        }
    }
    // Phase B: interior pixels gathered directly into registers
    float acc[NB];
    #pragma unroll
    for (int bb = 0; bb < NB; bb++) acc[bb] = 0.0f;
    int x = t;
    for (int a = 0; a < NA; a++) {
        ushort4 m = sm[a];
        if (x >= (int)m.x && x < (int)m.y) {
            int bin = g_bins[(size_t)(a * NH + y) * NW + x];
            const float4* r = (const float4*)(g_R + (size_t)(a * ND + bin) * NB);
            float4 r0 = r[0], r1 = r[1], r2 = r[2], r3 = r[3];
            acc[0] += r0.x;  acc[1] += r0.y;  acc[2] += r0.z;  acc[3] += r0.w;
            acc[4] += r1.x;  acc[5] += r1.y;  acc[6] += r1.z;  acc[7] += r1.w;
            acc[8] += r2.x;  acc[9] += r2.y;  acc[10] += r2.z; acc[11] += r2.w;
            acc[12] += r3.x; acc[13] += r3.y; acc[14] += r3.z; acc[15] += r3.w;
        }
    }
    __syncthreads();
    // Phase C: inclusive scan of Dsh along x per channel
    int w = t >> 5, lane = t & 31;
    for (int ch = w * 2; ch < w * 2 + 2; ch++) {
        float carry = 0.0f;
        for (int seg = 0; seg < 8; seg++) {
            int xx = seg * 32 + lane;
            float v = Dsh[xx * 17 + ch];
            #pragma unroll
            for (int off = 1; off < 32; off <<= 1) {
                float n = __shfl_up_sync(0xffffffffu, v, off);
                if (lane >= off) v += n;
            }
            v += carry;
            Dsh[xx * 17 + ch] = v;
            carry = __shfl_sync(0xffffffffu, v, 31);
        }
    }
    __syncthreads();
    // Phase D: image update, matching corr / A division semantics
    float* ip = g_img + (size_t)(y * NW + x) * NB;
    #pragma unroll
    for (int bb = 0; bb < NB; bb++) {
        float corr = acc[bb] + Dsh[x * 17 + bb];
        ip[bb] = ip[bb] + __fdiv_rn(corr, 180.0f);
    }
}

// global max over image (order-monotone uint encoding)
__global__ void k_max() {
    int i = blockIdx.x * blockDim.x + threadIdx.x;
    float m = -INFINITY;
    for (int j = i; j < NP * NB; j += gridDim.x * blockDim.x)
        m = fmaxf(m, g_img[j]);
    #pragma unroll
    for (int off = 16; off; off >>= 1)
        m = fmaxf(m, __shfl_xor_sync(0xffffffffu, m, off));
    if ((threadIdx.x & 31) == 0) {
        unsigned u = __float_as_uint(m);
        u = (u & 0x80000000u) ? ~u : (u | 0x80000000u);
        atomicMax(&g_maxbits, u);
    }
}

// output: clip(image, 0, gmax), transpose [pixel][b] -> [b][y][x]
__global__ void k_out(float* __restrict__ out, int n) {
    int o = blockIdx.x * blockDim.x + threadIdx.x;
    if (o >= n) return;
    unsigned u = g_maxbits;
    float gm = (u & 0x80000000u) ? __uint_as_float(u ^ 0x80000000u)
                                 : __uint_as_float(~u);
    int b = o >> 16;
    int p = o & 65535;
    float v = g_img[(size_t)p * NB + b];
    out[o] = fminf(fmaxf(v, 0.0f), gm);
}

extern "C" void kernel_launch(void* const* d_in, const int* in_sizes, int n_in,
                              void* d_out, int out_size) {
    const float* sino = (const float*)d_in[0];
    float* out = (float*)d_out;

    k_init<<<1024, 256>>>();
    k_angles<<<1, 256>>>();
    k_bins<<<NA, 256>>>();
    for (int it = 0; it < NT; it++) {
        k_prefix<<<NH, 256>>>();
        k_fp<<<NA, 256>>>(sino);
        k_bp<<<NH, 256>>>();
    }
    k_max<<<256, 256>>>();
    k_out<<<(out_size + 255) / 256, 256>>>(out, out_size);
}

// round 2
// speedup vs baseline: 1.0496x; 1.0496x over previous
#include <cuda_runtime.h>
#include <stdint.h>
#include <math.h>

#define NA 180
#define NH 256
#define NW 256
#define ND 256
#define NB 16
#define NT 5
#define NP (NH*NW)
#define NRC (NA*ND)
#define MAXRUNS (12*1024*1024)
#define MPI 3.14159265358979323846

// ---------------- device globals (no allocation allowed) ----------------
__device__ float g_C[NA];
__device__ float g_S[NA];
__device__ int   g_row[NA];
__device__ __align__(16) uint8_t g_bins[NA * NP];          // 11.8 MB
__device__ ushort4 g_meta[NA * NH];                         // xlo, xhi, leftbin, rightbin
__device__ __align__(64) float g_img[NP * NB];              // 4 MB, [pixel][batch]
__device__ __align__(64) float g_P[NH * 257 * NB];          // row prefix sums [y][x][b]
__device__ __align__(64) float g_R[NRC * NB];               // residual [a][d][b]
__device__ int g_cnt[NRC];                                  // run counts -> cursors
__device__ int g_start[NRC + 1];                            // exclusive offsets
__device__ unsigned g_runs[MAXRUNS];                        // packed runs y|x0<<8|x1<<17
__device__ unsigned g_maxbits;

// ---------------- init ----------------
__global__ void k_init() {
    int i = blockIdx.x * blockDim.x + threadIdx.x;
    int stride = gridDim.x * blockDim.x;
    for (int j = i; j < NP * NB; j += stride) g_img[j] = 0.0f;
    for (int j = i; j < NH * 257 * NB; j += stride) g_P[j] = 0.0f;
    for (int j = i; j < NRC; j += stride) g_cnt[j] = 0;
    if (i == 0) g_maxbits = 0u;
}

// angles / rows / trig, replicating numpy linspace + f32 ops
__global__ void k_angles() {
    int i = threadIdx.x;
    if (i < NA) {
        double ad = (double)i * (MPI / 179.0);
        float ang = (float)ad;
        if (i == NA - 1) ang = (float)MPI;              // linspace endpoint
        g_C[i] = (float)cos((double)ang);
        g_S[i] = (float)sin((double)ang);
        float r = __fmul_rn(__fdiv_rn(ang, (float)MPI), 179.0f);
        g_row[i] = (int)r;                               // trunc, nonneg
    }
}

// bins (exact f32 emulation, Markstein correctly-rounded /2pi) + meta + run counts
__global__ __launch_bounds__(256) void k_bins() {
    int a = blockIdx.x, y = threadIdx.x;
    const float TP  = (float)(2.0 * MPI);
    const float RCP = (float)(1.0 / (double)((float)(2.0 * MPI)));  // RN(1/TP)
    float c = g_C[a], s = g_S[a];
    float tY = __fmul_rn((float)y - 128.0f, s);
    uint8_t* brow = g_bins + (size_t)(a * NH + y) * NW;
    int prev = 0, lb = 0, xlo = 256, lastChange = 0;
    unsigned pk = 0;
    int cb = a * ND;
    for (int x = 0; x < NW; x++) {
        float xc = (float)x - 128.0f;
        float rot = __fadd_rn(__fmul_rn(xc, c), tY);
        // correctly-rounded rot / TP (Markstein, RN + fma)
        float q = __fmul_rn(rot, RCP);
        float r = __fmaf_rn(-TP, q, rot);
        q = __fmaf_rn(r, RCP, q);
        float v = __fmul_rn(q, 256.0f);
        v = truncf(v);
        v = fminf(fmaxf(v, 0.0f), 255.0f);
        int bin = (int)v;
        if (x == 0) { lb = bin; prev = bin; }
        else if (bin != prev) {
            atomicAdd(&g_cnt[cb + prev], 1);            // close previous run
            if (xlo == 256) xlo = x;
            lastChange = x;
            prev = bin;
        }
        pk |= ((unsigned)bin) << (8 * (x & 3));
        if ((x & 3) == 3) { *(unsigned*)(brow + x - 3) = pk; pk = 0; }
    }
    atomicAdd(&g_cnt[cb + prev], 1);                     // last run
    int rb = prev;
    int xhi = lastChange;
    if (xhi < xlo) xhi = xlo;
    g_meta[a * NH + y] = make_ushort4((unsigned short)xlo, (unsigned short)xhi,
                                      (unsigned short)lb, (unsigned short)rb);
}

// exclusive scan of g_cnt[46080] -> g_start, and reset g_cnt to cursor=start
__global__ __launch_bounds__(1024) void k_scan() {
    __shared__ int warpsum[32];
    int t = threadIdx.x;
    int i0 = t * 45;                                    // 1024*45 = 46080
    int s = 0;
    for (int j = 0; j < 45; j++) s += g_cnt[i0 + j];
    int lane = t & 31, w = t >> 5;
    int v = s;
    #pragma unroll
    for (int off = 1; off < 32; off <<= 1) {
        int n = __shfl_up_sync(0xffffffffu, v, off);
        if (lane >= off) v += n;
    }
    if (lane == 31) warpsum[w] = v;
    __syncthreads();
    if (w == 0) {
        int x = warpsum[lane];
        #pragma unroll
        for (int off = 1; off < 32; off <<= 1) {
            int n = __shfl_up_sync(0xffffffffu, x, off);
            if (lane >= off) x += n;
        }
        warpsum[lane] = x;
    }
    __syncthreads();
    int excl = v - s + (w > 0 ? warpsum[w - 1] : 0);
    int off = excl;
    for (int j = 0; j < 45; j++) {
        int cval = g_cnt[i0 + j];
        g_start[i0 + j] = off;
        g_cnt[i0 + j] = off;                            // cursor copy
        off += cval;
    }
    if (t == 1023) g_start[NRC] = off;
}

// fill run table: rewalk packed bins, bump per-(a,d) cursor
__global__ __launch_bounds__(256) void k_fill() {
    int a = blockIdx.x, y = threadIdx.x;
    const unsigned* bw = (const unsigned*)(g_bins + (size_t)(a * NH + y) * NW);
    int prev = -1, runStart = 0;
    int cb = a * ND;
    for (int x = 0; x < NW; x++) {
        int bin = (int)((bw[x >> 2] >> (8 * (x & 3))) & 255u);
        if (x == 0) prev = bin;
        else if (bin != prev) {
            int pos = atomicAdd(&g_cnt[cb + prev], 1);
            g_runs[pos] = (unsigned)y | ((unsigned)runStart << 8) | ((unsigned)x << 17);
            runStart = x;
            prev = bin;
        }
    }
    int pos = atomicAdd(&g_cnt[cb + prev], 1);
    g_runs[pos] = (unsigned)y | ((unsigned)runStart << 8) | (256u << 17);
}

// forward projection + residual: pure gather, warp per (a,d), zero atomics
__global__ __launch_bounds__(1024) void k_fp(const float* __restrict__ sino) {
    int t = threadIdx.x;
    int wi = blockIdx.x * 32 + (t >> 5);                // (a,d) index, 46080 total
    int lane = t & 31, half = lane >> 4, b = lane & 15;
    int base = g_start[wi], e = g_start[wi + 1];
    float acc = 0.0f;
    for (int r = base + half; r < e; r += 2) {
        unsigned rec = g_runs[r];
        int y = rec & 255;
        int x0 = (rec >> 8) & 511;
        int x1 = (rec >> 17) & 511;
        const float* Pr = g_P + (size_t)y * 257 * NB;
        acc += Pr[x1 * NB + b] - Pr[x0 * NB + b];
    }
    acc += __shfl_xor_sync(0xffffffffu, acc, 16);
    if (half == 0) {
        int a = wi >> 8, d = wi & 255;
        int row = g_row[a];
        g_R[(size_t)wi * NB + b] =
            sino[(size_t)b * (NA * ND) + row * ND + d] - acc;
    }
}

// back-projection + image update + fused row prefix sums (+ max on last iter)
__global__ __launch_bounds__(256) void k_bp(int last) {
    __shared__ float Dsh[257 * 17];
    __shared__ ushort4 sm[NA];
    __shared__ float blockmax[8];
    int y = blockIdx.x, t = threadIdx.x;
    for (int i = t; i < 257 * 17; i += 256) Dsh[i] = 0.0f;
    if (t < NA) sm[t] = g_meta[t * NH + y];
    __syncthreads();
    // Phase A: saturated/constant step contributions as difference array
    if (t < NA) {
        ushort4 m = sm[t];
        int xlo = m.x, xhi = m.y, lb = m.z, rb = m.w;
        const float* Ra = g_R + (size_t)t * ND * NB;
        if (xlo > 0) {
            const float* rl = Ra + lb * NB;
            #pragma unroll
            for (int bb = 0; bb < NB; bb++) {
                float v = rl[bb];
                atomicAdd(&Dsh[0 * 17 + bb], v);
                atomicAdd(&Dsh[xlo * 17 + bb], -v);
            }
        }
        if (xhi < 256) {
            const float* rr = Ra + rb * NB;
            #pragma unroll
            for (int bb = 0; bb < NB; bb++)
                atomicAdd(&Dsh[xhi * 17 + bb], rr[bb]);
        }
    }
    // Phase B: interior pixels gathered into registers
    float acc[NB];
    #pragma unroll
    for (int bb = 0; bb < NB; bb++) acc[bb] = 0.0f;
    int x = t;
    for (int a = 0; a < NA; a++) {
        ushort4 m = sm[a];
        if (x >= (int)m.x && x < (int)m.y) {
            int bin = g_bins[(size_t)(a * NH + y) * NW + x];
            const float4* r = (const float4*)(g_R + (size_t)(a * ND + bin) * NB);
            float4 r0 = r[0], r1 = r[1], r2 = r[2], r3 = r[3];
            acc[0] += r0.x;  acc[1] += r0.y;  acc[2] += r0.z;  acc[3] += r0.w;
            acc[4] += r1.x;  acc[5] += r1.y;  acc[6] += r1.z;  acc[7] += r1.w;
            acc[8] += r2.x;  acc[9] += r2.y;  acc[10] += r2.z; acc[11] += r2.w;
            acc[12] += r3.x; acc[13] += r3.y; acc[14] += r3.z; acc[15] += r3.w;
        }
    }
    __syncthreads();
    // Phase C: inclusive scan of diff array along x per channel
    int w = t >> 5, lane = t & 31;
    for (int ch = w * 2; ch < w * 2 + 2; ch++) {
        float carry = 0.0f;
        for (int seg = 0; seg < 8; seg++) {
            int xx = seg * 32 + lane;
            float v = Dsh[xx * 17 + ch];
            #pragma unroll
            for (int off = 1; off < 32; off <<= 1) {
                float n = __shfl_up_sync(0xffffffffu, v, off);
                if (lane >= off) v += n;
            }
            v += carry;
            Dsh[xx * 17 + ch] = v;
            carry = __shfl_sync(0xffffffffu, v, 31);
        }
    }
    __syncthreads();
    // Phase D: image update (corr / A semantics)
    float newv[NB];
    float* ip = g_img + (size_t)(y * NW + x) * NB;
    #pragma unroll
    for (int bb = 0; bb < NB; bb++) {
        float corr = acc[bb] + Dsh[x * 17 + bb];
        newv[bb] = ip[bb] + __fdiv_rn(corr, 180.0f);
    }
    __syncthreads();                         // all done reading Dsh
    #pragma unroll
    for (int bb = 0; bb < NB; bb++) {
        ip[bb] = newv[bb];
        Dsh[x * 17 + bb] = newv[bb];         // stage for prefix
    }
    if (last) {
        float m = newv[0];
        #pragma unroll
        for (int bb = 1; bb < NB; bb++) m = fmaxf(m, newv[bb]);
        #pragma unroll
        for (int off = 16; off; off >>= 1)
            m = fmaxf(m, __shfl_xor_sync(0xffffffffu, m, off));
        if (lane == 0) blockmax[w] = m;
    }
    __syncthreads();
    // Phase E: inclusive prefix sums of new row -> g_P (in-place smem scan)
    for (int ch = w * 2; ch < w * 2 + 2; ch++) {
        float carry = 0.0f;
        for (int seg = 0; seg < 8; seg++) {
            int xx = seg * 32 + lane;
            float v = Dsh[xx * 17 + ch];
            #pragma unroll
            for (int off = 1; off < 32; off <<= 1) {
                float n = __shfl_up_sync(0xffffffffu, v, off);
                if (lane >= off) v += n;
            }
            v += carry;
            Dsh[xx * 17 + ch] = v;
            carry = __shfl_sync(0xffffffffu, v, 31);
        }
    }
    __syncthreads();
    // coalesced copy-out (x=0 column of g_P stays 0 from k_init)
    for (int i = t; i < NW * NB; i += 256) {
        int xx = i >> 4, bb = i & 15;
        g_P[((size_t)y * 257 + xx + 1) * NB + bb] = Dsh[xx * 17 + bb];
    }
    if (last && t == 0) {
        float m = blockmax[0];
        #pragma unroll
        for (int k = 1; k < 8; k++) m = fmaxf(m, blockmax[k]);
        unsigned u = __float_as_uint(m);
        u = (u & 0x80000000u) ? ~u : (u | 0x80000000u);
        atomicMax(&g_maxbits, u);
    }
}

// output: clip(image, 0, gmax), coalesced transpose [p][b] -> [b][p]
__global__ __launch_bounds__(256) void k_out(float* __restrict__ out) {
    __shared__ float sh[256 * 17];
    int t = threadIdx.x;
    int p0 = blockIdx.x * 256;
    const float* src = g_img + (size_t)p0 * NB;
    for (int i = t; i < 256 * NB; i += 256) {
        int p = i >> 4, b = i & 15;
        sh[p * 17 + b] = src[i];
    }
    __syncthreads();
    unsigned u = g_maxbits;
    float gm = (u & 0x80000000u) ? __uint_as_float(u ^ 0x80000000u)
                                 : __uint_as_float(~u);
    #pragma unroll
    for (int b = 0; b < NB; b++) {
        float v = sh[t * 17 + b];
        out[(size_t)b * NP + p0 + t] = fminf(fmaxf(v, 0.0f), gm);
    }
}

extern "C" void kernel_launch(void* const* d_in, const int* in_sizes, int n_in,
                              void* d_out, int out_size) {
    const float* sino = (const float*)d_in[0];
    float* out = (float*)d_out;

    k_init<<<1024, 256>>>();
    k_angles<<<1, 256>>>();
    k_bins<<<NA, 256>>>();
    k_scan<<<1, 1024>>>();
    k_fill<<<NA, 256>>>();
    for (int it = 0; it < NT; it++) {
        k_fp<<<NRC / 32, 1024>>>(sino);
        k_bp<<<NH, 256>>>(it == NT - 1 ? 1 : 0);
    }
    k_out<<<256, 256>>>(out);
}

// round 4
// speedup vs baseline: 1.1709x; 1.1156x over previous
#include <cuda_runtime.h>
#include <stdint.h>
#include <math.h>

#define NA 180
#define NH 256
#define NW 256
#define ND 256
#define NB 16
#define NT 5
#define NP (NH*NW)
#define NRC (NA*ND)
#define CAP 256
#define MPI 3.14159265358979323846

// ---------------- device globals (no allocation allowed) ----------------
__device__ float g_C[NA];
__device__ float g_S[NA];
__device__ int   g_row[NA];
__device__ __align__(16) uint8_t g_bins[NA * NP];          // 11.8 MB
__device__ ushort4 g_meta[NA * NH];                         // xlo, xhi, leftbin, rightbin
__device__ __align__(64) float g_img[NP * NB];              // 4 MB, [pixel][batch]
__device__ __align__(64) float g_P[NH * 257 * NB];          // row prefix sums [y][x][b]
__device__ __align__(64) float g_R[NRC * NB];               // residual [a][d][b]
__device__ __align__(64) float g_SN[NRC * NB];              // sino rows transposed [a][d][b]
__device__ int g_cnt[NRC];                                  // per-slot run counts
__device__ unsigned g_runs[NRC * CAP];                      // packed runs y|x0<<8|x1<<17
__device__ unsigned g_maxbits;

// ---------------- init ----------------
__global__ void k_init() {
    int i = blockIdx.x * blockDim.x + threadIdx.x;
    int stride = gridDim.x * blockDim.x;
    for (int j = i; j < NP * NB; j += stride) g_img[j] = 0.0f;
    for (int j = i; j < NH * 257 * NB; j += stride) g_P[j] = 0.0f;
    for (int j = i; j < NRC; j += stride) g_cnt[j] = 0;
    if (i == 0) g_maxbits = 0u;
}

// angles / rows / trig, replicating numpy linspace + f32 ops
__global__ void k_angles() {
    int i = threadIdx.x;
    if (i < NA) {
        double ad = (double)i * (MPI / 179.0);
        float ang = (float)ad;
        if (i == NA - 1) ang = (float)MPI;              // linspace endpoint
        g_C[i] = (float)cos((double)ang);
        g_S[i] = (float)sin((double)ang);
        float r = __fmul_rn(__fdiv_rn(ang, (float)MPI), 179.0f);
        g_row[i] = (int)r;                               // trunc, nonneg
    }
}

// bins + meta + direct run-table fill (cap 256 exact) + sino transpose
__global__ __launch_bounds__(256) void k_binsfill(const float* __restrict__ sino) {
    int a = blockIdx.x, y = threadIdx.x;
    const float TP  = (float)(2.0 * MPI);
    const float RCP = (float)(1.0 / (double)((float)(2.0 * MPI)));  // RN(1/TP)
    float c = g_C[a], s = g_S[a];
    float tY = __fmul_rn((float)y - 128.0f, s);
    uint8_t* brow = g_bins + (size_t)(a * NH + y) * NW;
    int prev = 0, lb = 0, xlo = 256, lastChange = 0, runStart = 0;
    unsigned pk = 0;
    int cb = a * ND;
    for (int x = 0; x < NW; x++) {
        float xc = (float)x - 128.0f;
        float rot = __fadd_rn(__fmul_rn(xc, c), tY);
        // correctly-rounded rot / TP (Markstein, RN + fma)
        float q = __fmul_rn(rot, RCP);
        float r = __fmaf_rn(-TP, q, rot);
        q = __fmaf_rn(r, RCP, q);
        float v = __fmul_rn(q, 256.0f);
        v = truncf(v);
        v = fminf(fmaxf(v, 0.0f), 255.0f);
        int bin = (int)v;
        if (x == 0) { lb = bin; prev = bin; }
        else if (bin != prev) {
            int pos = atomicAdd(&g_cnt[cb + prev], 1);   // <=256 guaranteed (monotone)
            g_runs[(size_t)(cb + prev) * CAP + pos] =
                (unsigned)y | ((unsigned)runStart << 8) | ((unsigned)x << 17);
            runStart = x;
            if (xlo == 256) xlo = x;
            lastChange = x;
            prev = bin;
        }
        pk |= ((unsigned)bin) << (8 * (x & 3));
        if ((x & 3) == 3) { *(unsigned*)(brow + x - 3) = pk; pk = 0; }
    }
    {
        int pos = atomicAdd(&g_cnt[cb + prev], 1);
        g_runs[(size_t)(cb + prev) * CAP + pos] =
            (unsigned)y | ((unsigned)runStart << 8) | (256u << 17);
    }
    int rb = prev;
    int xhi = lastChange;
    if (xhi < xlo) xhi = xlo;
    g_meta[a * NH + y] = make_ushort4((unsigned short)xlo, (unsigned short)xhi,
                                      (unsigned short)lb, (unsigned short)rb);
    // sino transpose: g_SN[a][d][b] = sino[b][row][d]   (thread y acts as d)
    int row = g_row[a];
    int d = y;
    #pragma unroll
    for (int b = 0; b < NB; b++)
        g_SN[(size_t)(cb + d) * NB + b] = sino[(size_t)b * (NA * ND) + row * ND + d];
}

// forward projection + residual: pure gather, warp per (a,d), zero atomics
__global__ __launch_bounds__(1024) void k_fp() {
    int t = threadIdx.x;
    int wi = blockIdx.x * 32 + (t >> 5);                // (a,d) index, 46080 total
    int lane = t & 31, half = lane >> 4, b = lane & 15;
    int n = g_cnt[wi];
    const unsigned* runs = g_runs + (size_t)wi * CAP;
    float acc = 0.0f, acc2 = 0.0f;
    int r = half;
    for (; r + 2 < n; r += 4) {
        unsigned r1 = runs[r], r2 = runs[r + 2];
        const float* P1 = g_P + (size_t)(r1 & 255) * 257 * NB;
        const float* P2 = g_P + (size_t)(r2 & 255) * 257 * NB;
        acc  += P1[((r1 >> 17) & 511) * NB + b] - P1[((r1 >> 8) & 511) * NB + b];
        acc2 += P2[((r2 >> 17) & 511) * NB + b] - P2[((r2 >> 8) & 511) * NB + b];
    }
    for (; r < n; r += 2) {
        unsigned rec = runs[r];
        const float* Pr = g_P + (size_t)(rec & 255) * 257 * NB;
        acc += Pr[((rec >> 17) & 511) * NB + b] - Pr[((rec >> 8) & 511) * NB + b];
    }
    acc += acc2;
    acc += __shfl_xor_sync(0xffffffffu, acc, 16);
    if (half == 0)
        g_R[(size_t)wi * NB + b] = g_SN[(size_t)wi * NB + b] - acc;
}

// back-projection + image update + fused row prefix sums (+ max on last iter)
// 512 threads: x = t&255, h = t>>8 splits the 180-angle loop in half.
__global__ __launch_bounds__(512) void k_bp(int last) {
    __shared__ float Dsh[257 * 17];
    __shared__ float Acc[256 * 17];
    __shared__ ushort4 sm[NA];
    __shared__ float blockmax[8];
    int y = blockIdx.x, t = threadIdx.x;
    int x = t & 255, h = t >> 8;
    for (int i = t; i < 257 * 17; i += 512) Dsh[i] = 0.0f;
    if (t < NA) sm[t] = g_meta[t * NH + y];
    __syncthreads();
    // Phase A: saturated/constant step contributions as difference array
    if (t < NA) {
        ushort4 m = sm[t];
        int xlo = m.x, xhi = m.y, lb = m.z, rb = m.w;
        const float* Ra = g_R + (size_t)t * ND * NB;
        if (xlo > 0) {
            const float* rl = Ra + lb * NB;
            #pragma unroll
            for (int bb = 0; bb < NB; bb++) {
                float v = rl[bb];
                atomicAdd(&Dsh[0 * 17 + bb], v);
                atomicAdd(&Dsh[xlo * 17 + bb], -v);
            }
        }
        if (xhi < 256) {
            const float* rr = Ra + rb * NB;
            #pragma unroll
            for (int bb = 0; bb < NB; bb++)
                atomicAdd(&Dsh[xhi * 17 + bb], rr[bb]);
        }
    }
    // Phase B: interior pixels gathered into registers; angle range split by h
    float acc[NB];
    #pragma unroll
    for (int bb = 0; bb < NB; bb++) acc[bb] = 0.0f;
    for (int a = h * 90; a < h * 90 + 90; a++) {
        ushort4 m = sm[a];
        if (x >= (int)m.x && x < (int)m.y) {
            int bin = g_bins[(size_t)(a * NH + y) * NW + x];
            const float4* r = (const float4*)(g_R + (size_t)(a * ND + bin) * NB);
            float4 r0 = r[0], r1 = r[1], r2 = r[2], r3 = r[3];
            acc[0] += r0.x;  acc[1] += r0.y;  acc[2] += r0.z;  acc[3] += r0.w;
            acc[4] += r1.x;  acc[5] += r1.y;  acc[6] += r1.z;  acc[7] += r1.w;
            acc[8] += r2.x;  acc[9] += r2.y;  acc[10] += r2.z; acc[11] += r2.w;
            acc[12] += r3.x; acc[13] += r3.y; acc[14] += r3.z; acc[15] += r3.w;
        }
    }
    if (h == 1) {
        #pragma unroll
        for (int bb = 0; bb < NB; bb++) Acc[x * 17 + bb] = acc[bb];
    }
    __syncthreads();
    // Phase C: inclusive scan of diff array along x; warp w owns channel w
    int w = t >> 5, lane = t & 31;
    {
        int ch = w;
        float carry = 0.0f;
        for (int seg = 0; seg < 8; seg++) {
            int xx = seg * 32 + lane;
            float v = Dsh[xx * 17 + ch];
            #pragma unroll
            for (int off = 1; off < 32; off <<= 1) {
                float n = __shfl_up_sync(0xffffffffu, v, off);
                if (lane >= off) v += n;
            }
            v += carry;
            Dsh[xx * 17 + ch] = v;
            carry = __shfl_sync(0xffffffffu, v, 31);
        }
    }
    __syncthreads();
    // Phase D: image update (h==0 half holds the combined acc)
    if (h == 0) {
        float newv[NB];
        float* ip = g_img + (size_t)(y * NW + x) * NB;
        #pragma unroll
        for (int bb = 0; bb < NB; bb++) {
            float corr = acc[bb] + Acc[x * 17 + bb] + Dsh[x * 17 + bb];
            newv[bb] = ip[bb] + __fdiv_rn(corr, 180.0f);
        }
        #pragma unroll
        for (int bb = 0; bb < NB; bb++) {
            ip[bb] = newv[bb];
            Dsh[x * 17 + bb] = newv[bb];     // stage for prefix (own slot, safe)
        }
        if (last) {
            float m = newv[0];
            #pragma unroll
            for (int bb = 1; bb < NB; bb++) m = fmaxf(m, newv[bb]);
            #pragma unroll
            for (int off = 16; off; off >>= 1)
                m = fmaxf(m, __shfl_xor_sync(0xffffffffu, m, off));
            if (lane == 0) blockmax[w] = m;
        }
    }
    __syncthreads();
    // Phase E: inclusive prefix sums of new row -> g_P; warp w owns channel w
    {
        int ch = w;
        float carry = 0.0f;
        for (int seg = 0; seg < 8; seg++) {
            int xx = seg * 32 + lane;
            float v = Dsh[xx * 17 + ch];
            #pragma unroll
            for (int off = 1; off < 32; off <<= 1) {
                float n = __shfl_up_sync(0xffffffffu, v, off);
                if (lane >= off) v += n;
            }
            v += carry;
            Dsh[xx * 17 + ch] = v;
            carry = __shfl_sync(0xffffffffu, v, 31);
        }
    }
    __syncthreads();
    // coalesced copy-out (x=0 column of g_P stays 0 from k_init)
    for (int i = t; i < NW * NB; i += 512) {
        int xx = i >> 4, bb = i & 15;
        g_P[((size_t)y * 257 + xx + 1) * NB + bb] = Dsh[xx * 17 + bb];
    }
    if (last && t == 0) {
        float m = blockmax[0];
        #pragma unroll
        for (int k = 1; k < 8; k++) m = fmaxf(m, blockmax[k]);
        unsigned u = __float_as_uint(m);
        u = (u & 0x80000000u) ? ~u : (u | 0x80000000u);
        atomicMax(&g_maxbits, u);
    }
}

// output: clip(image, 0, gmax), coalesced transpose [p][b] -> [b][p]
__global__ __launch_bounds__(256) void k_out(float* __restrict__ out) {
    __shared__ float sh[256 * 17];
    int t = threadIdx.x;
    int p0 = blockIdx.x * 256;
    const float* src = g_img + (size_t)p0 * NB;
    for (int i = t; i < 256 * NB; i += 256) {
        int p = i >> 4, b = i & 15;
        sh[p * 17 + b] = src[i];
    }
    __syncthreads();
    unsigned u = g_maxbits;
    float gm = (u & 0x80000000u) ? __uint_as_float(u ^ 0x80000000u)
                                 : __uint_as_float(~u);
    #pragma unroll
    for (int b = 0; b < NB; b++) {
        float v = sh[t * 17 + b];
        out[(size_t)b * NP + p0 + t] = fminf(fmaxf(v, 0.0f), gm);
    }
}

extern "C" void kernel_launch(void* const* d_in, const int* in_sizes, int n_in,
                              void* d_out, int out_size) {
    const float* sino = (const float*)d_in[0];
    float* out = (float*)d_out;

    k_init<<<1024, 256>>>();
    k_angles<<<1, 256>>>();
    k_binsfill<<<NA, 256>>>(sino);
    for (int it = 0; it < NT; it++) {
        k_fp<<<NRC / 32, 1024>>>();          // launch #4 on it==0 -> ncu target
        k_bp<<<NH, 512>>>(it == NT - 1 ? 1 : 0);
    }
    k_out<<<256, 256>>>(out);
}

// round 5
// speedup vs baseline: 1.2007x; 1.0255x over previous
#include <cuda_runtime.h>
#include <stdint.h>
#include <math.h>

#define NA 180
#define NH 256
#define NW 256
#define ND 256
#define NB 16
#define NT 5
#define NP (NH*NW)
#define NRC (NA*ND)
#define CAP 256
#define MPI 3.14159265358979323846

// ---------------- device globals (no allocation allowed) ----------------
__device__ float g_C[NA];
__device__ float g_S[NA];
__device__ int   g_row[NA];
__device__ __align__(16) uint8_t g_bins[NA * NP];          // 11.8 MB
__device__ ushort4 g_meta[NA * NH];                         // xlo, xhi, leftbin, rightbin
__device__ __align__(64) float g_img[NP * NB];              // 4 MB, [pixel][batch]
__device__ __align__(64) float g_P[NH * 257 * NB];          // row prefix sums [y][x][b]
__device__ __align__(64) float g_R[NRC * NB];               // residual [a][d][b]
__device__ __align__(64) float g_SN[NRC * NB];              // sino rows transposed [a][d][b]
__device__ int g_cnt[NRC];                                  // per-slot run counts
__device__ unsigned g_runs[NRC * CAP];                      // packed runs y|x0<<8|x1<<17
__device__ unsigned g_maxbits;

// ---------------- init ----------------
__global__ void k_init() {
    int i = blockIdx.x * blockDim.x + threadIdx.x;
    int stride = gridDim.x * blockDim.x;
    for (int j = i; j < NP * NB; j += stride) g_img[j] = 0.0f;
    for (int j = i; j < NH * 257 * NB; j += stride) g_P[j] = 0.0f;
    for (int j = i; j < NRC; j += stride) g_cnt[j] = 0;
    if (i == 0) g_maxbits = 0u;
}

// angles / rows / trig, replicating numpy linspace + f32 ops
__global__ void k_angles() {
    int i = threadIdx.x;
    if (i < NA) {
        double ad = (double)i * (MPI / 179.0);
        float ang = (float)ad;
        if (i == NA - 1) ang = (float)MPI;              // linspace endpoint
        g_C[i] = (float)cos((double)ang);
        g_S[i] = (float)sin((double)ang);
        float r = __fmul_rn(__fdiv_rn(ang, (float)MPI), 179.0f);
        g_row[i] = (int)r;                               // trunc, nonneg
    }
}

// bins + meta + run fill (skipping terminal 0/255 bins) + sino transpose + R seed
__global__ __launch_bounds__(256) void k_binsfill(const float* __restrict__ sino) {
    int a = blockIdx.x, y = threadIdx.x;
    const float TP  = (float)(2.0 * MPI);
    const float RCP = (float)(1.0 / (double)((float)(2.0 * MPI)));  // RN(1/TP)
    float c = g_C[a], s = g_S[a];
    float tY = __fmul_rn((float)y - 128.0f, s);
    uint8_t* brow = g_bins + (size_t)(a * NH + y) * NW;
    int prev = 0, lb = 0, xlo = 256, lastChange = 0, runStart = 0;
    unsigned pk = 0;
    int cb = a * ND;
    for (int x = 0; x < NW; x++) {
        float xc = (float)x - 128.0f;
        float rot = __fadd_rn(__fmul_rn(xc, c), tY);
        // correctly-rounded rot / TP (Markstein, RN + fma)
        float q = __fmul_rn(rot, RCP);
        float r = __fmaf_rn(-TP, q, rot);
        q = __fmaf_rn(r, RCP, q);
        float v = __fmul_rn(q, 256.0f);
        v = truncf(v);
        v = fminf(fmaxf(v, 0.0f), 255.0f);
        int bin = (int)v;
        if (x == 0) { lb = bin; prev = bin; }
        else if (bin != prev) {
            if (prev != 0 && prev != 255) {              // terminal 0/255 handled by k_fp2
                int pos = atomicAdd(&g_cnt[cb + prev], 1);
                g_runs[(size_t)(cb + prev) * CAP + pos] =
                    (unsigned)y | ((unsigned)runStart << 8) | ((unsigned)x << 17);
            }
            runStart = x;
            if (xlo == 256) xlo = x;
            lastChange = x;
            prev = bin;
        }
        pk |= ((unsigned)bin) << (8 * (x & 3));
        if ((x & 3) == 3) { *(unsigned*)(brow + x - 3) = pk; pk = 0; }
    }
    if (prev != 0 && prev != 255) {
        int pos = atomicAdd(&g_cnt[cb + prev], 1);
        g_runs[(size_t)(cb + prev) * CAP + pos] =
            (unsigned)y | ((unsigned)runStart << 8) | (256u << 17);
    }
    int rb = prev;
    int xhi = lastChange;
    if (xhi < xlo) xhi = xlo;
    g_meta[a * NH + y] = make_ushort4((unsigned short)xlo, (unsigned short)xhi,
                                      (unsigned short)lb, (unsigned short)rb);
    // sino transpose + iteration-0 residual seed (image==0 -> R = sino)
    int row = g_row[a];
    int d = y;
    #pragma unroll
    for (int b = 0; b < NB; b++) {
        float sv = sino[(size_t)b * (NA * ND) + row * ND + d];
        g_SN[(size_t)(cb + d) * NB + b] = sv;
        g_R[(size_t)(cb + d) * NB + b] = sv;
    }
}

// forward projection + residual for interior bins: warp per (a,d), zero atomics
__global__ __launch_bounds__(256) void k_fp() {
    int t = threadIdx.x;
    int wi = blockIdx.x * 8 + (t >> 5);                 // (a,d) index, 46080 total
    int d = wi & 255;
    if (d == 0 || d == 255) return;                      // owned by k_fp2
    int lane = t & 31, half = lane >> 4, b = lane & 15;
    int n = g_cnt[wi];
    const unsigned* runs = g_runs + (size_t)wi * CAP;
    float acc = 0.0f, acc2 = 0.0f;
    int r = half;
    for (; r + 2 < n; r += 4) {
        unsigned r1 = runs[r], r2 = runs[r + 2];
        const float* P1 = g_P + (size_t)(r1 & 255) * 257 * NB;
        const float* P2 = g_P + (size_t)(r2 & 255) * 257 * NB;
        acc  += P1[((r1 >> 17) & 511) * NB + b] - P1[((r1 >> 8) & 511) * NB + b];
        acc2 += P2[((r2 >> 17) & 511) * NB + b] - P2[((r2 >> 8) & 511) * NB + b];
    }
    for (; r < n; r += 2) {
        unsigned rec = runs[r];
        const float* Pr = g_P + (size_t)(rec & 255) * 257 * NB;
        acc += Pr[((rec >> 17) & 511) * NB + b] - Pr[((rec >> 8) & 511) * NB + b];
    }
    acc += acc2;
    acc += __shfl_xor_sync(0xffffffffu, acc, 16);
    if (half == 0)
        g_R[(size_t)wi * NB + b] = g_SN[(size_t)wi * NB + b] - acc;
}

// FP + residual for terminal bins d in {0,255}: block per (a,side), meta-derived
__global__ __launch_bounds__(256) void k_fp2() {
    __shared__ ushort4 sm2[256];
    __shared__ float red[16 * 17];
    int bx = blockIdx.x;
    int a = bx >> 1;
    int d = (bx & 1) ? 255 : 0;
    int t = threadIdx.x;
    sm2[t] = g_meta[a * NH + t];
    __syncthreads();
    int b = t & 15, yg = t >> 4;
    float acc = 0.0f;
    #pragma unroll 4
    for (int i = 0; i < 16; i++) {
        int y = yg * 16 + i;
        ushort4 m = sm2[y];
        const float* Pr = g_P + (size_t)y * 257 * NB;
        if ((int)m.z == d)        acc += Pr[(int)m.x * NB + b];     // first run [0,xlo); const rows xlo=256 -> full row
        else if ((int)m.w == d)   acc += Pr[256 * NB + b] - Pr[(int)m.y * NB + b];  // last run [xhi,256)
    }
    red[yg * 17 + b] = acc;
    __syncthreads();
    if (t < 16) {
        float s = 0.0f;
        #pragma unroll
        for (int g = 0; g < 16; g++) s += red[g * 17 + t];
        int wi = a * ND + d;
        g_R[(size_t)wi * NB + t] = g_SN[(size_t)wi * NB + t] - s;
    }
}

// back-projection + image update + fused row prefix sums (+ max on last iter)
// 512 threads: x = t&255, h = t>>8 splits the 180-angle loop in half.
__global__ __launch_bounds__(512) void k_bp(int last) {
    __shared__ float Dsh[257 * 17];
    __shared__ float Acc[256 * 17];
    __shared__ ushort4 sm[NA];
    __shared__ float blockmax[8];
    int y = blockIdx.x, t = threadIdx.x;
    int x = t & 255, h = t >> 8;
    for (int i = t; i < 257 * 17; i += 512) Dsh[i] = 0.0f;
    if (t < NA) sm[t] = g_meta[t * NH + y];
    __syncthreads();
    // Phase A: saturated/constant step contributions as difference array
    if (t < NA) {
        ushort4 m = sm[t];
        int xlo = m.x, xhi = m.y, lb = m.z, rb = m.w;
        const float* Ra = g_R + (size_t)t * ND * NB;
        if (xlo > 0) {
            const float* rl = Ra + lb * NB;
            #pragma unroll
            for (int bb = 0; bb < NB; bb++) {
                float v = rl[bb];
                atomicAdd(&Dsh[0 * 17 + bb], v);
                atomicAdd(&Dsh[xlo * 17 + bb], -v);
            }
        }
        if (xhi < 256) {
            const float* rr = Ra + rb * NB;
            #pragma unroll
            for (int bb = 0; bb < NB; bb++)
                atomicAdd(&Dsh[xhi * 17 + bb], rr[bb]);
        }
    }
    // Phase B: interior pixels gathered into registers; angle range split by h
    float acc[NB];
    #pragma unroll
    for (int bb = 0; bb < NB; bb++) acc[bb] = 0.0f;
    for (int a = h * 90; a < h * 90 + 90; a++) {
        ushort4 m = sm[a];
        if (x >= (int)m.x && x < (int)m.y) {
            int bin = g_bins[(size_t)(a * NH + y) * NW + x];
            const float4* r = (const float4*)(g_R + (size_t)(a * ND + bin) * NB);
            float4 r0 = r[0], r1 = r[1], r2 = r[2], r3 = r[3];
            acc[0] += r0.x;  acc[1] += r0.y;  acc[2] += r0.z;  acc[3] += r0.w;
            acc[4] += r1.x;  acc[5] += r1.y;  acc[6] += r1.z;  acc[7] += r1.w;
            acc[8] += r2.x;  acc[9] += r2.y;  acc[10] += r2.z; acc[11] += r2.w;
            acc[12] += r3.x; acc[13] += r3.y; acc[14] += r3.z; acc[15] += r3.w;
        }
    }
    if (h == 1) {
        #pragma unroll
        for (int bb = 0; bb < NB; bb++) Acc[x * 17 + bb] = acc[bb];
    }
    __syncthreads();
    // Phase C: inclusive scan of diff array along x; warp w owns channel w
    int w = t >> 5, lane = t & 31;
    {
        int ch = w;
        float carry = 0.0f;
        for (int seg = 0; seg < 8; seg++) {
            int xx = seg * 32 + lane;
            float v = Dsh[xx * 17 + ch];
            #pragma unroll
            for (int off = 1; off < 32; off <<= 1) {
                float n = __shfl_up_sync(0xffffffffu, v, off);
                if (lane >= off) v += n;
            }
            v += carry;
            Dsh[xx * 17 + ch] = v;
            carry = __shfl_sync(0xffffffffu, v, 31);
        }
    }
    __syncthreads();
    // Phase D: image update (h==0 half holds the combined acc)
    if (h == 0) {
        float newv[NB];
        float* ip = g_img + (size_t)(y * NW + x) * NB;
        #pragma unroll
        for (int bb = 0; bb < NB; bb++) {
            float corr = acc[bb] + Acc[x * 17 + bb] + Dsh[x * 17 + bb];
            newv[bb] = ip[bb] + __fdiv_rn(corr, 180.0f);
        }
        #pragma unroll
        for (int bb = 0; bb < NB; bb++) {
            ip[bb] = newv[bb];
            Dsh[x * 17 + bb] = newv[bb];     // stage for prefix (own slot, safe)
        }
        if (last) {
            float m = newv[0];
            #pragma unroll
            for (int bb = 1; bb < NB; bb++) m = fmaxf(m, newv[bb]);
            #pragma unroll
            for (int off = 16; off; off >>= 1)
                m = fmaxf(m, __shfl_xor_sync(0xffffffffu, m, off));
            if (lane == 0) blockmax[w] = m;
        }
    }
    __syncthreads();
    // Phase E: inclusive prefix sums of new row -> g_P; warp w owns channel w
    {
        int ch = w;
        float carry = 0.0f;
        for (int seg = 0; seg < 8; seg++) {
            int xx = seg * 32 + lane;
            float v = Dsh[xx * 17 + ch];
            #pragma unroll
            for (int off = 1; off < 32; off <<= 1) {
                float n = __shfl_up_sync(0xffffffffu, v, off);
                if (lane >= off) v += n;
            }
            v += carry;
            Dsh[xx * 17 + ch] = v;
            carry = __shfl_sync(0xffffffffu, v, 31);
        }
    }
    __syncthreads();
    // coalesced copy-out (x=0 column of g_P stays 0 from k_init)
    for (int i = t; i < NW * NB; i += 512) {
        int xx = i >> 4, bb = i & 15;
        g_P[((size_t)y * 257 + xx + 1) * NB + bb] = Dsh[xx * 17 + bb];
    }
    if (last && t == 0) {
        float m = blockmax[0];
        #pragma unroll
        for (int k = 1; k < 8; k++) m = fmaxf(m, blockmax[k]);
        unsigned u = __float_as_uint(m);
        u = (u & 0x80000000u) ? ~u : (u | 0x80000000u);
        atomicMax(&g_maxbits, u);
    }
}

// output: clip(image, 0, gmax), coalesced transpose [p][b] -> [b][p]
__global__ __launch_bounds__(256) void k_out(float* __restrict__ out) {
    __shared__ float sh[256 * 17];
    int t = threadIdx.x;
    int p0 = blockIdx.x * 256;
    const float* src = g_img + (size_t)p0 * NB;
    for (int i = t; i < 256 * NB; i += 256) {
        int p = i >> 4, b = i & 15;
        sh[p * 17 + b] = src[i];
    }
    __syncthreads();
    unsigned u = g_maxbits;
    float gm = (u & 0x80000000u) ? __uint_as_float(u ^ 0x80000000u)
                                 : __uint_as_float(~u);
    #pragma unroll
    for (int b = 0; b < NB; b++) {
        float v = sh[t * 17 + b];
        out[(size_t)b * NP + p0 + t] = fminf(fmaxf(v, 0.0f), gm);
    }
}

extern "C" void kernel_launch(void* const* d_in, const int* in_sizes, int n_in,
                              void* d_out, int out_size) {
    const float* sino = (const float*)d_in[0];
    float* out = (float*)d_out;

    k_init<<<1024, 256>>>();
    k_angles<<<1, 256>>>();
    k_binsfill<<<NA, 256>>>(sino);       // seeds R = sino (image==0 residual)
    k_bp<<<NH, 512>>>(0);                // iteration 0; launch #4 -> ncu target
    for (int it = 1; it < NT; it++) {
        k_fp<<<NRC / 8, 256>>>();
        k_fp2<<<NA * 2, 256>>>();
        k_bp<<<NH, 512>>>(it == NT - 1 ? 1 : 0);
    }
    k_out<<<256, 256>>>(out);
}